// round 1
// baseline (speedup 1.0000x reference)
#include <cuda_runtime.h>
#include <cuda_bf16.h>

#define DIM 128
#define NNB 64   // neighbors per row

// One block per batch row. 128 threads: thread t owns output dim t.
// Shared: 64 neighbor indices + 64 softmax weights.
__global__ void __launch_bounds__(128, 8)
net_gather_kernel(const int* __restrict__ data_r,
                  const int* __restrict__ data_e,
                  const int* __restrict__ rel,
                  const int* __restrict__ pos_id,
                  const int* __restrict__ neg_id,
                  const float* __restrict__ ent_emb,
                  const float* __restrict__ edge_w,
                  const float* __restrict__ rel_emb,
                  float* __restrict__ out,
                  int B)
{
    const int b   = blockIdx.x;
    const int tid = threadIdx.x;

    __shared__ float s_w[NNB];
    __shared__ int   s_e[NNB];

    // Stage neighbor entity indices and edge logits.
    if (tid < NNB) {
        s_e[tid] = data_e[b * NNB + tid];
        // reuse s_w to hold raw logits first
        s_w[tid] = __ldg(&edge_w[data_r[b * NNB + tid]]);
    }
    __syncthreads();

    // Warp 0 computes softmax over the 64 logits (2 per lane).
    if (tid < 32) {
        float l0 = s_w[tid];
        float l1 = s_w[tid + 32];
        float m = fmaxf(l0, l1);
        #pragma unroll
        for (int off = 16; off > 0; off >>= 1)
            m = fmaxf(m, __shfl_xor_sync(0xffffffffu, m, off));
        float e0 = __expf(l0 - m);
        float e1 = __expf(l1 - m);
        float s = e0 + e1;
        #pragma unroll
        for (int off = 16; off > 0; off >>= 1)
            s += __shfl_xor_sync(0xffffffffu, s, off);
        float inv = __frcp_rn(s);
        s_w[tid]      = e0 * inv;
        s_w[tid + 32] = e1 * inv;
    }
    __syncthreads();

    // Weighted gather-sum: each thread owns dim `tid`.
    // 4 independent accumulators for memory-level parallelism.
    float a0 = 0.f, a1 = 0.f, a2 = 0.f, a3 = 0.f;
    #pragma unroll
    for (int j = 0; j < NNB; j += 4) {
        long i0 = (long)s_e[j + 0] * DIM;
        long i1 = (long)s_e[j + 1] * DIM;
        long i2 = (long)s_e[j + 2] * DIM;
        long i3 = (long)s_e[j + 3] * DIM;
        float v0 = __ldg(&ent_emb[i0 + tid]);
        float v1 = __ldg(&ent_emb[i1 + tid]);
        float v2 = __ldg(&ent_emb[i2 + tid]);
        float v3 = __ldg(&ent_emb[i3 + tid]);
        a0 = fmaf(s_w[j + 0], v0, a0);
        a1 = fmaf(s_w[j + 1], v1, a1);
        a2 = fmaf(s_w[j + 2], v2, a2);
        a3 = fmaf(s_w[j + 3], v3, a3);
    }
    float acc = (a0 + a1) + (a2 + a3);

    // out_t = Eh + rel_emb[rel[b]]
    const int   r   = rel[b];
    const float rv  = __ldg(&rel_emb[(long)r * DIM + tid]);
    const long  bd  = (long)b * DIM + tid;
    const long  BD  = (long)B * DIM;
    out[bd] = acc + rv;

    // pos / neg entity lookups
    const long pi = (long)pos_id[b] * DIM;
    const long ni = (long)neg_id[b] * DIM;
    out[BD + bd]     = __ldg(&ent_emb[pi + tid]);
    out[2 * BD + bd] = __ldg(&ent_emb[ni + tid]);
}

extern "C" void kernel_launch(void* const* d_in, const int* in_sizes, int n_in,
                              void* d_out, int out_size)
{
    const int*   data_r  = (const int*)  d_in[0];
    const int*   data_e  = (const int*)  d_in[1];
    const int*   rel     = (const int*)  d_in[2];
    const int*   pos_id  = (const int*)  d_in[3];
    const int*   neg_id  = (const int*)  d_in[4];
    const float* ent_emb = (const float*)d_in[5];
    const float* edge_w  = (const float*)d_in[6];
    const float* rel_emb = (const float*)d_in[7];
    float* out = (float*)d_out;

    const int B = in_sizes[2];  // rel has B elements

    net_gather_kernel<<<B, 128>>>(data_r, data_e, rel, pos_id, neg_id,
                                  ent_emb, edge_w, rel_emb, out, B);
}

// round 2
// speedup vs baseline: 1.1100x; 1.1100x over previous
#include <cuda_runtime.h>
#include <cuda_bf16.h>

#define DIM 128
#define NNB 64   // neighbors per row

// One block per batch row. 128 threads: thread t owns output dim t.
__global__ void __launch_bounds__(128, 8)
net_gather_kernel(const int* __restrict__ data_r,
                  const int* __restrict__ data_e,
                  const int* __restrict__ rel,
                  const int* __restrict__ pos_id,
                  const int* __restrict__ neg_id,
                  const float* __restrict__ ent_emb,
                  const float* __restrict__ edge_w,
                  const float* __restrict__ rel_emb,
                  float* __restrict__ out,
                  int B)
{
    const int b   = blockIdx.x;
    const int tid = threadIdx.x;

    __shared__ float s_w[NNB];
    __shared__ int   s_e[NNB];   // pre-scaled by DIM (fits in int32: 500001*128 < 2^31)

    // Stage neighbor entity indices and edge logits.
    if (tid < NNB) {
        s_e[tid] = data_e[b * NNB + tid] * DIM;
        s_w[tid] = __ldg(&edge_w[data_r[b * NNB + tid]]);   // raw logits first
    }
    __syncthreads();

    // Independent per-row lookups issued EARLY so they overlap the gather loop.
    const int   r  = rel[b];
    const float rv = __ldg(&rel_emb[r * DIM + tid]);
    const float pv = __ldg(&ent_emb[pos_id[b] * DIM + tid]);
    const float nv = __ldg(&ent_emb[neg_id[b] * DIM + tid]);

    // Warp 0 computes softmax over the 64 logits (2 per lane).
    if (tid < 32) {
        float l0 = s_w[tid];
        float l1 = s_w[tid + 32];
        float m = fmaxf(l0, l1);
        #pragma unroll
        for (int off = 16; off > 0; off >>= 1)
            m = fmaxf(m, __shfl_xor_sync(0xffffffffu, m, off));
        float e0 = __expf(l0 - m);
        float e1 = __expf(l1 - m);
        float s = e0 + e1;
        #pragma unroll
        for (int off = 16; off > 0; off >>= 1)
            s += __shfl_xor_sync(0xffffffffu, s, off);
        float inv = __frcp_rn(s);
        s_w[tid]      = e0 * inv;
        s_w[tid + 32] = e1 * inv;
    }
    __syncthreads();

    // Weighted gather-sum: 8 independent loads in flight per thread for MLP.
    float a0 = 0.f, a1 = 0.f, a2 = 0.f, a3 = 0.f;
    float a4 = 0.f, a5 = 0.f, a6 = 0.f, a7 = 0.f;
    #pragma unroll
    for (int j = 0; j < NNB; j += 8) {
        int i0 = s_e[j + 0], i1 = s_e[j + 1], i2 = s_e[j + 2], i3 = s_e[j + 3];
        int i4 = s_e[j + 4], i5 = s_e[j + 5], i6 = s_e[j + 6], i7 = s_e[j + 7];
        float v0 = __ldg(&ent_emb[i0 + tid]);
        float v1 = __ldg(&ent_emb[i1 + tid]);
        float v2 = __ldg(&ent_emb[i2 + tid]);
        float v3 = __ldg(&ent_emb[i3 + tid]);
        float v4 = __ldg(&ent_emb[i4 + tid]);
        float v5 = __ldg(&ent_emb[i5 + tid]);
        float v6 = __ldg(&ent_emb[i6 + tid]);
        float v7 = __ldg(&ent_emb[i7 + tid]);
        a0 = fmaf(s_w[j + 0], v0, a0);
        a1 = fmaf(s_w[j + 1], v1, a1);
        a2 = fmaf(s_w[j + 2], v2, a2);
        a3 = fmaf(s_w[j + 3], v3, a3);
        a4 = fmaf(s_w[j + 4], v4, a4);
        a5 = fmaf(s_w[j + 5], v5, a5);
        a6 = fmaf(s_w[j + 6], v6, a6);
        a7 = fmaf(s_w[j + 7], v7, a7);
    }
    float acc = ((a0 + a1) + (a2 + a3)) + ((a4 + a5) + (a6 + a7));

    const int bd = b * DIM + tid;
    const int BD = B * DIM;
    out[bd]          = acc + rv;
    out[BD + bd]     = pv;
    out[2 * BD + bd] = nv;
}

extern "C" void kernel_launch(void* const* d_in, const int* in_sizes, int n_in,
                              void* d_out, int out_size)
{
    const int*   data_r  = (const int*)  d_in[0];
    const int*   data_e  = (const int*)  d_in[1];
    const int*   rel     = (const int*)  d_in[2];
    const int*   pos_id  = (const int*)  d_in[3];
    const int*   neg_id  = (const int*)  d_in[4];
    const float* ent_emb = (const float*)d_in[5];
    const float* edge_w  = (const float*)d_in[6];
    const float* rel_emb = (const float*)d_in[7];
    float* out = (float*)d_out;

    const int B = in_sizes[2];  // rel has B elements

    net_gather_kernel<<<B, 128>>>(data_r, data_e, rel, pos_id, neg_id,
                                  ent_emb, edge_w, rel_emb, out, B);
}

// round 3
// speedup vs baseline: 1.3092x; 1.1795x over previous
#include <cuda_runtime.h>
#include <cuda_bf16.h>

#define DIM   128
#define NNB   64
#define WARPS 8        // rows per block

// One warp per batch row. Lane l owns dims [4l, 4l+3] (float4).
// One LDG.128 per warp = one full 512B embedding row in flight.
__global__ void __launch_bounds__(256, 4)
net_gather_kernel(const int* __restrict__ data_r,
                  const int* __restrict__ data_e,
                  const int* __restrict__ rel,
                  const int* __restrict__ pos_id,
                  const int* __restrict__ neg_id,
                  const float* __restrict__ ent_emb,
                  const float* __restrict__ edge_w,
                  const float* __restrict__ rel_emb,
                  float* __restrict__ out,
                  int B)
{
    const int w    = threadIdx.x >> 5;
    const int lane = threadIdx.x & 31;
    const int b    = blockIdx.x * WARPS + w;

    __shared__ int   s_e[WARPS][NNB];   // entity row index * 32 (float4 stride)
    __shared__ float s_w[WARPS][NNB];   // softmax weights

    // Stage indices (prescaled to float4 row offset) and edge logits.
    const int base = b * NNB;
    s_e[w][lane]      = data_e[base + lane]      * (DIM / 4);
    s_e[w][lane + 32] = data_e[base + lane + 32] * (DIM / 4);
    float l0 = __ldg(&edge_w[data_r[base + lane]]);
    float l1 = __ldg(&edge_w[data_r[base + lane + 32]]);

    // Warp-local softmax over 64 logits (2 per lane).
    float m = fmaxf(l0, l1);
    #pragma unroll
    for (int off = 16; off > 0; off >>= 1)
        m = fmaxf(m, __shfl_xor_sync(0xffffffffu, m, off));
    float x0 = __expf(l0 - m);
    float x1 = __expf(l1 - m);
    float s = x0 + x1;
    #pragma unroll
    for (int off = 16; off > 0; off >>= 1)
        s += __shfl_xor_sync(0xffffffffu, s, off);
    float inv = __frcp_rn(s);
    s_w[w][lane]      = x0 * inv;
    s_w[w][lane + 32] = x1 * inv;
    __syncwarp();

    const float4* __restrict__ emb4 = (const float4*)ent_emb;   // row stride 32

    // Independent per-row lookups issued early (overlap with gather loop).
    float4 rv = __ldg(&((const float4*)rel_emb)[rel[b] * (DIM / 4) + lane]);
    float4 pv = __ldg(&emb4[pos_id[b] * (DIM / 4) + lane]);
    float4 nv = __ldg(&emb4[neg_id[b] * (DIM / 4) + lane]);

    // Weighted gather-sum: 8 LDG.128 in flight per chunk, 2 float4 accumulators.
    float4 A = make_float4(0.f, 0.f, 0.f, 0.f);
    float4 C = make_float4(0.f, 0.f, 0.f, 0.f);
    #pragma unroll
    for (int j = 0; j < NNB; j += 8) {
        float4 v[8];
        float  wt[8];
        #pragma unroll
        for (int k = 0; k < 8; k++) {
            v[k]  = __ldg(&emb4[s_e[w][j + k] + lane]);
            wt[k] = s_w[w][j + k];
        }
        #pragma unroll
        for (int k = 0; k < 8; k += 2) {
            A.x = fmaf(wt[k], v[k].x, A.x);
            A.y = fmaf(wt[k], v[k].y, A.y);
            A.z = fmaf(wt[k], v[k].z, A.z);
            A.w = fmaf(wt[k], v[k].w, A.w);
            C.x = fmaf(wt[k + 1], v[k + 1].x, C.x);
            C.y = fmaf(wt[k + 1], v[k + 1].y, C.y);
            C.z = fmaf(wt[k + 1], v[k + 1].z, C.z);
            C.w = fmaf(wt[k + 1], v[k + 1].w, C.w);
        }
    }

    float4 o;
    o.x = A.x + C.x + rv.x;
    o.y = A.y + C.y + rv.y;
    o.z = A.z + C.z + rv.z;
    o.w = A.w + C.w + rv.w;

    float4* out4 = (float4*)out;
    const int bd = b * (DIM / 4) + lane;
    const int BD = B * (DIM / 4);
    out4[bd]          = o;
    out4[BD + bd]     = pv;
    out4[2 * BD + bd] = nv;
}

extern "C" void kernel_launch(void* const* d_in, const int* in_sizes, int n_in,
                              void* d_out, int out_size)
{
    const int*   data_r  = (const int*)  d_in[0];
    const int*   data_e  = (const int*)  d_in[1];
    const int*   rel     = (const int*)  d_in[2];
    const int*   pos_id  = (const int*)  d_in[3];
    const int*   neg_id  = (const int*)  d_in[4];
    const float* ent_emb = (const float*)d_in[5];
    const float* edge_w  = (const float*)d_in[6];
    const float* rel_emb = (const float*)d_in[7];
    float* out = (float*)d_out;

    const int B = in_sizes[2];  // rel has B elements

    net_gather_kernel<<<B / WARPS, 32 * WARPS>>>(data_r, data_e, rel,
                                                 pos_id, neg_id,
                                                 ent_emb, edge_w, rel_emb,
                                                 out, B);
}

// round 4
// speedup vs baseline: 1.3232x; 1.0107x over previous
#include <cuda_runtime.h>
#include <cuda_bf16.h>

#define DIM   128
#define NNB   64
#define WARPS 2        // rows per block (small blocks -> fine-grained load balance)

// One warp per batch row. Lane l owns dims [4l, 4l+3] (float4).
// One LDG.128 per warp = one full 512B embedding row in flight.
__global__ void __launch_bounds__(32 * WARPS, 16)
net_gather_kernel(const int* __restrict__ data_r,
                  const int* __restrict__ data_e,
                  const int* __restrict__ rel,
                  const int* __restrict__ pos_id,
                  const int* __restrict__ neg_id,
                  const float* __restrict__ ent_emb,
                  const float* __restrict__ edge_w,
                  const float* __restrict__ rel_emb,
                  float* __restrict__ out,
                  int B)
{
    const int w    = threadIdx.x >> 5;
    const int lane = threadIdx.x & 31;
    const int b    = blockIdx.x * WARPS + w;

    __shared__ int   s_e[WARPS][NNB];   // entity row index * 32 (float4 stride)
    __shared__ float s_w[WARPS][NNB];   // softmax weights

    // Stage indices (prescaled to float4 row offset) and edge logits.
    const int base = b * NNB;
    s_e[w][lane]      = data_e[base + lane]      * (DIM / 4);
    s_e[w][lane + 32] = data_e[base + lane + 32] * (DIM / 4);
    float l0 = __ldg(&edge_w[data_r[base + lane]]);
    float l1 = __ldg(&edge_w[data_r[base + lane + 32]]);

    // Warp-local softmax over 64 logits (2 per lane).
    float m = fmaxf(l0, l1);
    #pragma unroll
    for (int off = 16; off > 0; off >>= 1)
        m = fmaxf(m, __shfl_xor_sync(0xffffffffu, m, off));
    float x0 = __expf(l0 - m);
    float x1 = __expf(l1 - m);
    float s = x0 + x1;
    #pragma unroll
    for (int off = 16; off > 0; off >>= 1)
        s += __shfl_xor_sync(0xffffffffu, s, off);
    float inv = __frcp_rn(s);
    s_w[w][lane]      = x0 * inv;
    s_w[w][lane + 32] = x1 * inv;
    __syncwarp();

    const float4* __restrict__ emb4 = (const float4*)ent_emb;   // row stride 32

    // Independent per-row lookups issued early (overlap with gather loop).
    float4 rv = __ldg(&((const float4*)rel_emb)[rel[b] * (DIM / 4) + lane]);
    float4 pv = __ldg(&emb4[pos_id[b] * (DIM / 4) + lane]);
    float4 nv = __ldg(&emb4[neg_id[b] * (DIM / 4) + lane]);

    // Weighted gather-sum: 8 LDG.128 in flight per chunk, 2 float4 accumulators.
    float4 A = make_float4(0.f, 0.f, 0.f, 0.f);
    float4 C = make_float4(0.f, 0.f, 0.f, 0.f);
    #pragma unroll
    for (int j = 0; j < NNB; j += 8) {
        float4 v[8];
        float  wt[8];
        #pragma unroll
        for (int k = 0; k < 8; k++) {
            v[k]  = __ldg(&emb4[s_e[w][j + k] + lane]);
            wt[k] = s_w[w][j + k];
        }
        #pragma unroll
        for (int k = 0; k < 8; k += 2) {
            A.x = fmaf(wt[k], v[k].x, A.x);
            A.y = fmaf(wt[k], v[k].y, A.y);
            A.z = fmaf(wt[k], v[k].z, A.z);
            A.w = fmaf(wt[k], v[k].w, A.w);
            C.x = fmaf(wt[k + 1], v[k + 1].x, C.x);
            C.y = fmaf(wt[k + 1], v[k + 1].y, C.y);
            C.z = fmaf(wt[k + 1], v[k + 1].z, C.z);
            C.w = fmaf(wt[k + 1], v[k + 1].w, C.w);
        }
    }

    float4 o;
    o.x = A.x + C.x + rv.x;
    o.y = A.y + C.y + rv.y;
    o.z = A.z + C.z + rv.z;
    o.w = A.w + C.w + rv.w;

    float4* out4 = (float4*)out;
    const int bd = b * (DIM / 4) + lane;
    const int BD = B * (DIM / 4);
    out4[bd]          = o;
    out4[BD + bd]     = pv;
    out4[2 * BD + bd] = nv;
}

extern "C" void kernel_launch(void* const* d_in, const int* in_sizes, int n_in,
                              void* d_out, int out_size)
{
    const int*   data_r  = (const int*)  d_in[0];
    const int*   data_e  = (const int*)  d_in[1];
    const int*   rel     = (const int*)  d_in[2];
    const int*   pos_id  = (const int*)  d_in[3];
    const int*   neg_id  = (const int*)  d_in[4];
    const float* ent_emb = (const float*)d_in[5];
    const float* edge_w  = (const float*)d_in[6];
    const float* rel_emb = (const float*)d_in[7];
    float* out = (float*)d_out;

    const int B = in_sizes[2];  // rel has B elements

    net_gather_kernel<<<B / WARPS, 32 * WARPS>>>(data_r, data_e, rel,
                                                 pos_id, neg_id,
                                                 ent_emb, edge_w, rel_emb,
                                                 out, B);
}